// round 11
// baseline (speedup 1.0000x reference)
#include <cuda_runtime.h>
#include <cuda_fp16.h>
#include <math.h>
#include <stdint.h>

// ---------------- problem dims ----------------
#define BDIM 4
#define TDIM 2048
#define DDIM 512
#define EDIM 4
#define CDIM 1024
#define HEDIM 512
#define ODIM 512
#define ECDIM 4096

typedef __half f16;

// ---------------- operand storage (no cudaMalloc allowed) ----------------
__device__ f16 g_dmT[(size_t)BDIM * ECDIM * TDIM];   // dmask^T  [B][E*C][T]
__device__ f16 g_cmb[(size_t)BDIM * TDIM * ECDIM];   // combine  [B][T][E*C]
__device__ f16 g_x  [(size_t)BDIM * TDIM * DDIM];
__device__ f16 g_w1 [(size_t)EDIM * DDIM * HEDIM];
__device__ f16 g_w2 [(size_t)EDIM * HEDIM * ODIM];
__device__ f16 g_xd [(size_t)BDIM * ECDIM * DDIM];
__device__ f16 g_h  [(size_t)BDIM * ECDIM * HEDIM];
__device__ f16 g_y  [(size_t)BDIM * ECDIM * ODIM];

// ---------------- helpers ----------------
__device__ __forceinline__ uint32_t pack_h2(float a, float b) {
    __half2 p = __floats2half2_rn(a, b);
    return *reinterpret_cast<uint32_t*>(&p);
}

// ---------------- conversion kernels ----------------
__global__ void conv_ew(const float* __restrict__ s, f16* __restrict__ d,
                        long long n4) {
    long long i = (long long)blockIdx.x * blockDim.x + threadIdx.x;
    if (i < n4) {
        float4 v = reinterpret_cast<const float4*>(s)[i];
        uint2 h;
        h.x = pack_h2(v.x, v.y); h.y = pack_h2(v.z, v.w);
        reinterpret_cast<uint2*>(d)[i] = h;
    }
}
__global__ void tr_one(const float* __restrict__ s, f16* __restrict__ d,
                       int R, int Cc) {
    __shared__ float t[64][33];
    const int c0 = blockIdx.x * 32, r0 = blockIdx.y * 64;
    const size_t zoff = (size_t)blockIdx.z * R * Cc;
    const float* S = s + zoff;
    const int tx = threadIdx.x & 31, ty = threadIdx.x >> 5;
#pragma unroll
    for (int i = 0; i < 8; i++) {
        int r = ty + i * 8;
        t[r][tx] = S[(size_t)(r0 + r) * Cc + c0 + tx];
    }
    __syncthreads();
    const int rr = threadIdx.x >> 3, pair = threadIdx.x & 7;
#pragma unroll
    for (int i = 0; i < 4; i++) {
        int tcol = (pair + i * 8) * 2;
        float a = t[tcol][rr], b = t[tcol + 1][rr];
        size_t o = zoff + (size_t)(c0 + rr) * R + r0 + tcol;
        *reinterpret_cast<uint32_t*>(d + o) = pack_h2(a, b);
    }
}

// ---------------- GEMM tile config ----------------
constexpr int BM = 128, BN = 128, BK = 64;
constexpr int THREADS = 256;
constexpr int A_PITCH = 144;                 // 128B row + 16B pad
constexpr int B_PITCH = 272;                 // 256B row + 16B pad
constexpr int OFF_B   = 128 * A_PITCH;       // 18432
constexpr int STAGE   = OFF_B + 64 * B_PITCH; // 35840 -> round up
constexpr int STAGE_SZ = 36864;
constexpr int NSTG    = 3;
constexpr int DATA_OFF = 128;                // mbarriers live in [0,128)
constexpr int SMEM_TOTAL = DATA_OFF + NSTG * STAGE_SZ;  // 110720
constexpr uint32_t TXBYTES = 128 * 128 + 64 * 256;      // 32768

__device__ __forceinline__ uint32_t smem_u32(const void* p) {
    uint32_t a;
    asm("{ .reg .u64 t; cvta.to.shared.u64 t, %1; cvt.u32.u64 %0, t; }"
        : "=r"(a) : "l"(p));
    return a;
}
__device__ __forceinline__ void ldsm4(uint32_t* r, uint32_t addr) {
    asm volatile("ldmatrix.sync.aligned.m8n8.x4.shared.b16 {%0,%1,%2,%3}, [%4];"
                 : "=r"(r[0]), "=r"(r[1]), "=r"(r[2]), "=r"(r[3]) : "r"(addr));
}
__device__ __forceinline__ void ldsm4t(uint32_t* r, uint32_t addr) {
    asm volatile("ldmatrix.sync.aligned.m8n8.x4.trans.shared.b16 {%0,%1,%2,%3}, [%4];"
                 : "=r"(r[0]), "=r"(r[1]), "=r"(r[2]), "=r"(r[3]) : "r"(addr));
}
__device__ __forceinline__ void mma_f16(float* d, const uint32_t* a, const uint32_t* b) {
    asm volatile(
        "mma.sync.aligned.m16n8k16.row.col.f32.f16.f16.f32 "
        "{%0,%1,%2,%3}, {%4,%5,%6,%7}, {%8,%9}, {%0,%1,%2,%3};"
        : "+f"(d[0]), "+f"(d[1]), "+f"(d[2]), "+f"(d[3])
        : "r"(a[0]), "r"(a[1]), "r"(a[2]), "r"(a[3]), "r"(b[0]), "r"(b[1]));
}
__device__ __forceinline__ void mbar_init(uint32_t mb, uint32_t cnt) {
    asm volatile("mbarrier.init.shared.b64 [%0], %1;" :: "r"(mb), "r"(cnt) : "memory");
}
__device__ __forceinline__ void mbar_expect(uint32_t mb, uint32_t tx) {
    asm volatile("mbarrier.arrive.expect_tx.shared.b64 _, [%0], %1;"
                 :: "r"(mb), "r"(tx) : "memory");
}
__device__ __forceinline__ void mbar_wait(uint32_t mb, uint32_t parity) {
    asm volatile(
        "{\n\t.reg .pred P;\n\t"
        "W_%=:\n\t"
        "mbarrier.try_wait.parity.acquire.cta.shared::cta.b64 P, [%0], %1, 0x989680;\n\t"
        "@P bra.uni D_%=;\n\t"
        "bra.uni W_%=;\n\t"
        "D_%=:\n\t}"
        :: "r"(mb), "r"(parity) : "memory");
}
__device__ __forceinline__ void bulk_cp(uint32_t dst, const void* src,
                                        uint32_t bytes, uint32_t mb) {
    asm volatile(
        "cp.async.bulk.shared::cluster.global.mbarrier::complete_tx::bytes "
        "[%0], [%1], %2, [%3];"
        :: "r"(dst), "l"(src), "r"(bytes), "r"(mb) : "memory");
}

// ---------------- main GEMM kernel ----------------
// CTA 128x128, BK=64, warp tile 64x32, 2 CTAs/SM, bulk-copy staging.
template<int OUTM, bool GELU_, bool BIAS_>
__global__ __launch_bounds__(THREADS, 2)
void moe_gemm(const f16* __restrict__ Ab, const f16* __restrict__ Bb,
              float* __restrict__ Cf, f16* __restrict__ Ch,
              const float* __restrict__ biasBase,
              int lda, int ldb, int ldc, int KT, int zMod,
              long long sA1, long long sA2, long long sB1, long long sB2,
              long long sC1, long long sC2, long long sBias2)
{
    extern __shared__ char smem[];
    const int tid  = threadIdx.x;
    const int lane = tid & 31;
    const int wid  = tid >> 5;
    const int wm   = (wid & 1) * 64;
    const int wn   = (wid >> 1) * 32;

    const int z = blockIdx.z;
    const int zq = z / zMod, zr = z % zMod;
    const f16* A = Ab + zq * sA1 + zr * sA2;
    const f16* B = Bb + zq * sB1 + zr * sB2;
    const long long coff = zq * sC1 + zr * sC2;
    const float* bias = BIAS_ ? biasBase + zr * sBias2 : nullptr;

    const int m0 = blockIdx.y * BM;
    const int n0 = blockIdx.x * BN;
    const uint32_t sbase = smem_u32(smem);

    float acc[4][4][4];
#pragma unroll
    for (int i = 0; i < 4; i++)
#pragma unroll
        for (int j = 0; j < 4; j++)
#pragma unroll
            for (int c = 0; c < 4; c++) acc[i][j][c] = 0.f;

    // warp 0 issues one stage: 128 A-row + 64 B-row bulk copies
    auto issue = [&](int s) {
        if (s >= KT) return;
        const uint32_t stg = sbase + DATA_OFF + (s % NSTG) * STAGE_SZ;
        const uint32_t mb  = sbase + (s % NSTG) * 8;
        if (lane == 0) mbar_expect(mb, TXBYTES);
        __syncwarp();
        const f16* As = A + (size_t)m0 * lda + (size_t)s * BK;
        for (int r = lane; r < 128; r += 32)
            bulk_cp(stg + r * A_PITCH, As + (size_t)r * lda, 128, mb);
        const f16* Bs = B + (size_t)s * BK * ldb + n0;
        for (int k = lane; k < 64; k += 32)
            bulk_cp(stg + OFF_B + k * B_PITCH, Bs + (size_t)k * ldb, 256, mb);
    };

    if (tid == 0) {
#pragma unroll
        for (int s = 0; s < NSTG; s++) mbar_init(sbase + s * 8, 1);
    }
    __syncthreads();
    if (wid == 0) { issue(0); issue(1); }

    for (int it = 0; it < KT; ++it) {
        __syncthreads();                 // all done with stage it-1 before re-arm
        if (wid == 0) issue(it + 2);
        mbar_wait(sbase + (it % NSTG) * 8, (it / NSTG) & 1);

        const uint32_t cur = sbase + DATA_OFF + (it % NSTG) * STAGE_SZ;
#pragma unroll
        for (int kh = 0; kh < 4; kh++) {
            uint32_t ar[4][4];
#pragma unroll
            for (int mf = 0; mf < 4; mf++) {
                int row = wm + mf * 16 + (lane & 15);
                uint32_t addr = cur + row * A_PITCH + kh * 32 + (lane >> 4) * 16;
                ldsm4(ar[mf], addr);
            }
            uint32_t br[2][4];
#pragma unroll
            for (int nb = 0; nb < 2; nb++) {
                int k = kh * 16 + ((lane >> 3) & 1) * 8 + (lane & 7);
                int nchunk = ((wn + nb * 16) >> 3) + (lane >> 4);
                uint32_t addr = cur + OFF_B + k * B_PITCH + nchunk * 16;
                ldsm4t(br[nb], addr);
            }
#pragma unroll
            for (int mf = 0; mf < 4; mf++)
#pragma unroll
                for (int nf = 0; nf < 4; nf++)
                    mma_f16(acc[mf][nf], ar[mf], &br[nf >> 1][(nf & 1) * 2]);
        }
    }

    // ---- epilogue ----
    const int g = lane >> 2, t = lane & 3;
#pragma unroll
    for (int mf = 0; mf < 4; mf++) {
#pragma unroll
        for (int nf = 0; nf < 4; nf++) {
            int row = m0 + wm + mf * 16 + g;
            int col = n0 + wn + nf * 8 + t * 2;
            float v0 = acc[mf][nf][0], v1 = acc[mf][nf][1];
            float v2 = acc[mf][nf][2], v3 = acc[mf][nf][3];
            if (BIAS_) {
                float2 bv = *reinterpret_cast<const float2*>(bias + col);
                v0 += bv.x; v1 += bv.y; v2 += bv.x; v3 += bv.y;
            }
            if (GELU_) {
                v0 = 0.5f * v0 * (1.0f + erff(v0 * 0.70710678118654752f));
                v1 = 0.5f * v1 * (1.0f + erff(v1 * 0.70710678118654752f));
                v2 = 0.5f * v2 * (1.0f + erff(v2 * 0.70710678118654752f));
                v3 = 0.5f * v3 * (1.0f + erff(v3 * 0.70710678118654752f));
            }
            size_t o0 = (size_t)(coff + (size_t)row * ldc + col);
            size_t o1 = (size_t)(coff + (size_t)(row + 8) * ldc + col);
            if (OUTM == 0) {
                *reinterpret_cast<float2*>(Cf + o0) = make_float2(v0, v1);
                *reinterpret_cast<float2*>(Cf + o1) = make_float2(v2, v3);
            } else {
                *reinterpret_cast<uint32_t*>(Ch + o0) = pack_h2(v0, v1);
                *reinterpret_cast<uint32_t*>(Ch + o1) = pack_h2(v2, v3);
            }
        }
    }
}

// ---------------- launcher ----------------
extern "C" void kernel_launch(void* const* d_in, const int* in_sizes, int n_in,
                              void* d_out, int out_size)
{
    const float* x     = (const float*)d_in[0];
    const float* dmask = (const float*)d_in[1];
    const float* comb  = (const float*)d_in[2];
    const float* w1    = (const float*)d_in[3];
    const float* b1    = (const float*)d_in[4];
    const float* w2f   = (const float*)d_in[5];
    const float* b2    = (const float*)d_in[6];
    float* out = (float*)d_out;

    f16 *dmT, *cmb, *xs, *w1s, *w2s, *xd, *hh, *yy;
    cudaGetSymbolAddress((void**)&dmT, g_dmT);
    cudaGetSymbolAddress((void**)&cmb, g_cmb);
    cudaGetSymbolAddress((void**)&xs,  g_x);
    cudaGetSymbolAddress((void**)&w1s, g_w1);
    cudaGetSymbolAddress((void**)&w2s, g_w2);
    cudaGetSymbolAddress((void**)&xd,  g_xd);
    cudaGetSymbolAddress((void**)&hh,  g_h);
    cudaGetSymbolAddress((void**)&yy,  g_y);

    cudaFuncSetAttribute(moe_gemm<2, false, false>,
                         cudaFuncAttributeMaxDynamicSharedMemorySize, SMEM_TOTAL);
    cudaFuncSetAttribute(moe_gemm<2, true,  true>,
                         cudaFuncAttributeMaxDynamicSharedMemorySize, SMEM_TOTAL);
    cudaFuncSetAttribute(moe_gemm<0, false, true>,
                         cudaFuncAttributeMaxDynamicSharedMemorySize, SMEM_TOTAL);

    // ---- conversions (all single fp16) ----
    tr_one<<<dim3(ECDIM / 32, TDIM / 64, BDIM), 256>>>(dmask, dmT, TDIM, ECDIM);
    {
        long long n4 = (long long)BDIM * TDIM * ECDIM / 4;
        conv_ew<<<(unsigned)((n4 + 255) / 256), 256>>>(comb, cmb, n4);
    }
    {
        long long n4 = (long long)BDIM * TDIM * DDIM / 4;
        conv_ew<<<(unsigned)((n4 + 255) / 256), 256>>>(x, xs, n4);
    }
    {
        long long n4 = (long long)EDIM * DDIM * HEDIM / 4;
        conv_ew<<<(unsigned)((n4 + 255) / 256), 256>>>(w1, w1s, n4);
        conv_ew<<<(unsigned)((n4 + 255) / 256), 256>>>(w2f, w2s, n4);
    }

    // ---- K1: xd[b][EC][D] = dmT[b][EC][T] @ x[b][T][D] ----
    moe_gemm<2, false, false>
        <<<dim3(DDIM / BN, ECDIM / BM, BDIM), THREADS, SMEM_TOTAL>>>(
        dmT, xs, nullptr, xd, nullptr,
        TDIM, DDIM, DDIM, TDIM / BK, /*zMod*/ 1,
        (long long)ECDIM * TDIM, 0, (long long)TDIM * DDIM, 0,
        (long long)ECDIM * DDIM, 0, 0);

    // ---- K2: h[b,e][C][HE] = gelu(xd_{b,e}[C][D] @ w1_e[D][HE] + b1_e) ----
    moe_gemm<2, true, true>
        <<<dim3(HEDIM / BN, CDIM / BM, BDIM * EDIM), THREADS, SMEM_TOTAL>>>(
        xd, w1s, nullptr, hh, b1,
        DDIM, HEDIM, HEDIM, DDIM / BK, /*zMod*/ EDIM,
        (long long)EDIM * CDIM * DDIM, (long long)CDIM * DDIM,
        0, (long long)DDIM * HEDIM,
        (long long)EDIM * CDIM * HEDIM, (long long)CDIM * HEDIM,
        (long long)HEDIM);

    // ---- K3: y[b,e][C][O] = h_{b,e}[C][HE] @ w2_e[HE][O] ----
    moe_gemm<2, false, false>
        <<<dim3(ODIM / BN, CDIM / BM, BDIM * EDIM), THREADS, SMEM_TOTAL>>>(
        hh, w2s, nullptr, yy, nullptr,
        HEDIM, ODIM, ODIM, HEDIM / BK, /*zMod*/ EDIM,
        (long long)EDIM * CDIM * HEDIM, (long long)CDIM * HEDIM,
        0, (long long)HEDIM * ODIM,
        (long long)EDIM * CDIM * ODIM, (long long)CDIM * ODIM,
        0);

    // ---- K4: out[b][T][O] = comb[b][T][EC] @ y[b][EC][O] + b2 ----
    moe_gemm<0, false, true>
        <<<dim3(ODIM / BN, TDIM / BM, BDIM), THREADS, SMEM_TOTAL>>>(
        cmb, yy, out, nullptr, b2,
        ECDIM, ODIM, ODIM, ECDIM / BK, /*zMod*/ 1,
        (long long)TDIM * ECDIM, 0, (long long)ECDIM * ODIM, 0,
        (long long)TDIM * ODIM, 0, 0);
}

// round 12
// speedup vs baseline: 2.9679x; 2.9679x over previous
#include <cuda_runtime.h>
#include <cuda_fp16.h>
#include <math.h>
#include <stdint.h>

// ---------------- problem dims ----------------
#define BDIM 4
#define TDIM 2048
#define DDIM 512
#define EDIM 4
#define CDIM 1024
#define HEDIM 512
#define ODIM 512
#define ECDIM 4096

typedef __half f16;

// ---------------- operand storage (no cudaMalloc allowed) ----------------
__device__ f16 g_dm [(size_t)BDIM * TDIM * ECDIM];   // dmask (native layout, f16)
__device__ f16 g_cmb[(size_t)BDIM * TDIM * ECDIM];   // combine
__device__ f16 g_x  [(size_t)BDIM * TDIM * DDIM];
__device__ f16 g_w1 [(size_t)EDIM * DDIM * HEDIM];
__device__ f16 g_w2 [(size_t)EDIM * HEDIM * ODIM];
__device__ f16 g_xd [(size_t)BDIM * ECDIM * DDIM];
__device__ f16 g_h  [(size_t)BDIM * ECDIM * HEDIM];
__device__ f16 g_y  [(size_t)BDIM * ECDIM * ODIM];

// ---------------- helpers ----------------
__device__ __forceinline__ uint32_t pack_h2(float a, float b) {
    __half2 p = __floats2half2_rn(a, b);
    return *reinterpret_cast<uint32_t*>(&p);
}

// ---------------- conversion kernel ----------------
__global__ void conv_ew(const float* __restrict__ s, f16* __restrict__ d,
                        long long n4) {
    long long i = (long long)blockIdx.x * blockDim.x + threadIdx.x;
    if (i < n4) {
        float4 v = reinterpret_cast<const float4*>(s)[i];
        uint2 h;
        h.x = pack_h2(v.x, v.y); h.y = pack_h2(v.z, v.w);
        reinterpret_cast<uint2*>(d)[i] = h;
    }
}

// ---------------- GEMM tile config ----------------
constexpr int BM = 128, BN = 128, BK = 32;
constexpr int THREADS = 256;
constexpr int OFF_B  = 8192;
constexpr int STAGE  = 16384;
constexpr int NSTG   = 4;
constexpr int SMEM_TOTAL = NSTG * STAGE;   // 64 KB -> 2 CTAs/SM

__device__ __forceinline__ int a_off(int m, int kc) {   // A row-major tile, rows 64B
    return m * 64 + ((kc ^ ((m >> 1) & 3)) << 4);
}
__device__ __forceinline__ int b_off(int k, int nc) {   // 256B rows, nc 0..15
    return k * 256 + ((nc ^ (k & 7)) << 4);
}
__device__ __forceinline__ uint32_t smem_u32(const void* p) {
    uint32_t a;
    asm("{ .reg .u64 t; cvta.to.shared.u64 t, %1; cvt.u32.u64 %0, t; }"
        : "=r"(a) : "l"(p));
    return a;
}
__device__ __forceinline__ void ldsm4(uint32_t* r, uint32_t addr) {
    asm volatile("ldmatrix.sync.aligned.m8n8.x4.shared.b16 {%0,%1,%2,%3}, [%4];"
                 : "=r"(r[0]), "=r"(r[1]), "=r"(r[2]), "=r"(r[3]) : "r"(addr));
}
__device__ __forceinline__ void ldsm4t(uint32_t* r, uint32_t addr) {
    asm volatile("ldmatrix.sync.aligned.m8n8.x4.trans.shared.b16 {%0,%1,%2,%3}, [%4];"
                 : "=r"(r[0]), "=r"(r[1]), "=r"(r[2]), "=r"(r[3]) : "r"(addr));
}
__device__ __forceinline__ void mma_f16(float* d, const uint32_t* a, const uint32_t* b) {
    asm volatile(
        "mma.sync.aligned.m16n8k16.row.col.f32.f16.f16.f32 "
        "{%0,%1,%2,%3}, {%4,%5,%6,%7}, {%8,%9}, {%0,%1,%2,%3};"
        : "+f"(d[0]), "+f"(d[1]), "+f"(d[2]), "+f"(d[3])
        : "r"(a[0]), "r"(a[1]), "r"(a[2]), "r"(a[3]), "r"(b[0]), "r"(b[1]));
}
__device__ __forceinline__ void cp16(uint32_t dst, const void* src) {
    asm volatile("cp.async.cg.shared.global [%0], [%1], 16;" :: "r"(dst), "l"(src));
}
__device__ __forceinline__ void cp_commit() {
    asm volatile("cp.async.commit_group;" ::: "memory");
}
template<int N>
__device__ __forceinline__ void cp_wait() {
    asm volatile("cp.async.wait_group %0;" :: "n"(N) : "memory");
}

// ---------------- main GEMM kernel ----------------
// CTA 128x128, warp tile 64x32, 2 CTAs/SM, 1-pass fp16, fp32 accum.
// ATR=1: A is stored K-major in gmem ([k][m], row stride lda); the smem A tile
//        uses the B-style [k][m-chunks] layout and ldmatrix.trans.
// ATR=0: A row-major [m][k].
// Two-level z indexing: off = (z/zMod)*s1 + (z%zMod)*s2 for A, B, C; bias by zr.
// OUTM: 0 = fp32 out, 2 = single f16 out.
template<int ATR, int OUTM, bool GELU_, bool BIAS_>
__global__ __launch_bounds__(THREADS, 2)
void moe_gemm(const f16* __restrict__ Ab, const f16* __restrict__ Bb,
              float* __restrict__ Cf, f16* __restrict__ Ch,
              const float* __restrict__ biasBase,
              int lda, int ldb, int ldc, int KT, int zMod,
              long long sA1, long long sA2, long long sB1, long long sB2,
              long long sC1, long long sC2, long long sBias2)
{
    extern __shared__ char smem[];
    const int tid  = threadIdx.x;
    const int lane = tid & 31;
    const int wid  = tid >> 5;
    const int wm   = (wid & 1) * 64;
    const int wn   = (wid >> 1) * 32;

    const int z = blockIdx.z;
    const int zq = z / zMod, zr = z % zMod;
    const f16* A = Ab + zq * sA1 + zr * sA2;
    const f16* B = Bb + zq * sB1 + zr * sB2;
    const long long coff = zq * sC1 + zr * sC2;
    const float* bias = BIAS_ ? biasBase + zr * sBias2 : nullptr;

    const int m0 = blockIdx.y * BM;
    const int n0 = blockIdx.x * BN;
    const uint32_t sbase = smem_u32(smem);

    float acc[4][4][4];
#pragma unroll
    for (int i = 0; i < 4; i++)
#pragma unroll
        for (int j = 0; j < 4; j++)
#pragma unroll
            for (int c = 0; c < 4; c++) acc[i][j][c] = 0.f;

    auto issue = [&](int it) {
        if (it < KT) {
            const uint32_t st = sbase + (it & (NSTG - 1)) * STAGE;
            const int k0 = it * BK;
#pragma unroll
            for (int i = 0; i < 2; i++) {
                int c = tid + i * THREADS;          // 512 chunks A
                if (ATR) {
                    int k = c >> 4, mc = c & 15;    // A gmem row k, 16B at m-chunk
                    cp16(st + b_off(k, mc),
                         A + (size_t)(k0 + k) * lda + m0 + mc * 8);
                } else {
                    int m = c >> 2, kc = c & 3;
                    cp16(st + a_off(m, kc),
                         A + (size_t)(m0 + m) * lda + k0 + kc * 8);
                }
            }
#pragma unroll
            for (int i = 0; i < 2; i++) {
                int c = tid + i * THREADS;          // 512 chunks B
                int k = c >> 4, nc = c & 15;
                cp16(st + OFF_B + b_off(k, nc),
                     B + (size_t)(k0 + k) * ldb + n0 + nc * 8);
            }
        }
        cp_commit();
    };

    issue(0); issue(1); issue(2);

    for (int it = 0; it < KT; ++it) {
        cp_wait<2>();
        __syncthreads();
        issue(it + 3);

        const uint32_t cur = sbase + (it & (NSTG - 1)) * STAGE;
#pragma unroll
        for (int kh = 0; kh < 2; kh++) {
            uint32_t ar[4][4];
#pragma unroll
            for (int mf = 0; mf < 4; mf++) {
                if (ATR) {
                    // groups: a0{mlow,klow} a1{mhigh,klow} a2{mlow,khigh} a3{mhigh,khigh}
                    int k = kh * 16 + (lane >> 4) * 8 + (lane & 7);
                    int mchunk = ((wm + mf * 16) >> 3) + ((lane >> 3) & 1);
                    ldsm4t(ar[mf], cur + b_off(k, mchunk));
                } else {
                    int row = wm + mf * 16 + (lane & 15);
                    int chunk = kh * 2 + (lane >> 4);
                    ldsm4(ar[mf], cur + a_off(row, chunk));
                }
            }
            uint32_t br[2][4];
#pragma unroll
            for (int nb = 0; nb < 2; nb++) {
                int k = kh * 16 + ((lane >> 3) & 1) * 8 + (lane & 7);
                int nchunk = ((wn + nb * 16) >> 3) + (lane >> 4);
                ldsm4t(br[nb], cur + OFF_B + b_off(k, nchunk));
            }
#pragma unroll
            for (int mf = 0; mf < 4; mf++)
#pragma unroll
                for (int nf = 0; nf < 4; nf++)
                    mma_f16(acc[mf][nf], ar[mf], &br[nf >> 1][(nf & 1) * 2]);
        }
    }

    // ---- epilogue ----
    const int g = lane >> 2, t = lane & 3;
#pragma unroll
    for (int mf = 0; mf < 4; mf++) {
#pragma unroll
        for (int nf = 0; nf < 4; nf++) {
            int row = m0 + wm + mf * 16 + g;
            int col = n0 + wn + nf * 8 + t * 2;
            float v0 = acc[mf][nf][0], v1 = acc[mf][nf][1];
            float v2 = acc[mf][nf][2], v3 = acc[mf][nf][3];
            if (BIAS_) {
                float2 bv = *reinterpret_cast<const float2*>(bias + col);
                v0 += bv.x; v1 += bv.y; v2 += bv.x; v3 += bv.y;
            }
            if (GELU_) {
                v0 = 0.5f * v0 * (1.0f + erff(v0 * 0.70710678118654752f));
                v1 = 0.5f * v1 * (1.0f + erff(v1 * 0.70710678118654752f));
                v2 = 0.5f * v2 * (1.0f + erff(v2 * 0.70710678118654752f));
                v3 = 0.5f * v3 * (1.0f + erff(v3 * 0.70710678118654752f));
            }
            size_t o0 = (size_t)(coff + (size_t)row * ldc + col);
            size_t o1 = (size_t)(coff + (size_t)(row + 8) * ldc + col);
            if (OUTM == 0) {
                *reinterpret_cast<float2*>(Cf + o0) = make_float2(v0, v1);
                *reinterpret_cast<float2*>(Cf + o1) = make_float2(v2, v3);
            } else {
                *reinterpret_cast<uint32_t*>(Ch + o0) = pack_h2(v0, v1);
                *reinterpret_cast<uint32_t*>(Ch + o1) = pack_h2(v2, v3);
            }
        }
    }
}

// ---------------- launcher ----------------
extern "C" void kernel_launch(void* const* d_in, const int* in_sizes, int n_in,
                              void* d_out, int out_size)
{
    const float* x     = (const float*)d_in[0];
    const float* dmask = (const float*)d_in[1];
    const float* comb  = (const float*)d_in[2];
    const float* w1    = (const float*)d_in[3];
    const float* b1    = (const float*)d_in[4];
    const float* w2f   = (const float*)d_in[5];
    const float* b2    = (const float*)d_in[6];
    float* out = (float*)d_out;

    f16 *dm, *cmb, *xs, *w1s, *w2s, *xd, *hh, *yy;
    cudaGetSymbolAddress((void**)&dm,  g_dm);
    cudaGetSymbolAddress((void**)&cmb, g_cmb);
    cudaGetSymbolAddress((void**)&xs,  g_x);
    cudaGetSymbolAddress((void**)&w1s, g_w1);
    cudaGetSymbolAddress((void**)&w2s, g_w2);
    cudaGetSymbolAddress((void**)&xd,  g_xd);
    cudaGetSymbolAddress((void**)&hh,  g_h);
    cudaGetSymbolAddress((void**)&yy,  g_y);

    cudaFuncSetAttribute(moe_gemm<1, 2, false, false>,
                         cudaFuncAttributeMaxDynamicSharedMemorySize, SMEM_TOTAL);
    cudaFuncSetAttribute(moe_gemm<0, 2, true,  true>,
                         cudaFuncAttributeMaxDynamicSharedMemorySize, SMEM_TOTAL);
    cudaFuncSetAttribute(moe_gemm<0, 2, false, false>,
                         cudaFuncAttributeMaxDynamicSharedMemorySize, SMEM_TOTAL);
    cudaFuncSetAttribute(moe_gemm<0, 0, false, true>,
                         cudaFuncAttributeMaxDynamicSharedMemorySize, SMEM_TOTAL);

    // ---- conversions (all elementwise fp16, no transpose needed) ----
    {
        long long n4 = (long long)BDIM * TDIM * ECDIM / 4;
        conv_ew<<<(unsigned)((n4 + 255) / 256), 256>>>(dmask, dm, n4);
        conv_ew<<<(unsigned)((n4 + 255) / 256), 256>>>(comb, cmb, n4);
    }
    {
        long long n4 = (long long)BDIM * TDIM * DDIM / 4;
        conv_ew<<<(unsigned)((n4 + 255) / 256), 256>>>(x, xs, n4);
    }
    {
        long long n4 = (long long)EDIM * DDIM * HEDIM / 4;
        conv_ew<<<(unsigned)((n4 + 255) / 256), 256>>>(w1, w1s, n4);
        conv_ew<<<(unsigned)((n4 + 255) / 256), 256>>>(w2f, w2s, n4);
    }

    // ---- K1: xd[b][EC][D] = dmask_b^T[EC][T] @ x[b][T][D]  (ATR: A=[T][EC]) ----
    moe_gemm<1, 2, false, false>
        <<<dim3(DDIM / BN, ECDIM / BM, BDIM), THREADS, SMEM_TOTAL>>>(
        dm, xs, nullptr, xd, nullptr,
        ECDIM, DDIM, DDIM, TDIM / BK, /*zMod*/ 1,
        (long long)TDIM * ECDIM, 0, (long long)TDIM * DDIM, 0,
        (long long)ECDIM * DDIM, 0, 0);

    // ---- K2: h[b,e][C][HE] = gelu(xd_{b,e}[C][D] @ w1_e[D][HE] + b1_e) ----
    moe_gemm<0, 2, true, true>
        <<<dim3(HEDIM / BN, CDIM / BM, BDIM * EDIM), THREADS, SMEM_TOTAL>>>(
        xd, w1s, nullptr, hh, b1,
        DDIM, HEDIM, HEDIM, DDIM / BK, /*zMod*/ EDIM,
        (long long)EDIM * CDIM * DDIM, (long long)CDIM * DDIM,
        0, (long long)DDIM * HEDIM,
        (long long)EDIM * CDIM * HEDIM, (long long)CDIM * HEDIM,
        (long long)HEDIM);

    // ---- K3: y[b,e][C][O] = h_{b,e}[C][HE] @ w2_e[HE][O] ----
    moe_gemm<0, 2, false, false>
        <<<dim3(ODIM / BN, CDIM / BM, BDIM * EDIM), THREADS, SMEM_TOTAL>>>(
        hh, w2s, nullptr, yy, nullptr,
        HEDIM, ODIM, ODIM, HEDIM / BK, /*zMod*/ EDIM,
        (long long)EDIM * CDIM * HEDIM, (long long)CDIM * HEDIM,
        0, (long long)HEDIM * ODIM,
        (long long)EDIM * CDIM * ODIM, (long long)CDIM * ODIM,
        0);

    // ---- K4: out[b][T][O] = comb[b][T][EC] @ y[b][EC][O] + b2 ----
    moe_gemm<0, 0, false, true>
        <<<dim3(ODIM / BN, TDIM / BM, BDIM), THREADS, SMEM_TOTAL>>>(
        cmb, yy, out, nullptr, b2,
        ECDIM, ODIM, ODIM, ECDIM / BK, /*zMod*/ 1,
        (long long)TDIM * ECDIM, 0, (long long)ECDIM * ODIM, 0,
        (long long)TDIM * ODIM, 0, 0);
}

// round 13
// speedup vs baseline: 2.9854x; 1.0059x over previous
#include <cuda_runtime.h>
#include <cuda_fp16.h>
#include <math.h>
#include <stdint.h>

// ---------------- problem dims ----------------
#define BDIM 4
#define TDIM 2048
#define DDIM 512
#define EDIM 4
#define CDIM 1024
#define HEDIM 512
#define ODIM 512
#define ECDIM 4096

typedef __half f16;

// ---------------- operand storage (no cudaMalloc allowed) ----------------
__device__ f16 g_dm [(size_t)BDIM * TDIM * ECDIM];   // dmask (native layout, f16)
__device__ f16 g_cmb[(size_t)BDIM * TDIM * ECDIM];   // combine
__device__ f16 g_x  [(size_t)BDIM * TDIM * DDIM];
__device__ f16 g_w1 [(size_t)EDIM * DDIM * HEDIM];
__device__ f16 g_w2 [(size_t)EDIM * HEDIM * ODIM];
__device__ f16 g_xd [(size_t)BDIM * ECDIM * DDIM];
__device__ f16 g_h  [(size_t)BDIM * ECDIM * HEDIM];
__device__ f16 g_y  [(size_t)BDIM * ECDIM * ODIM];

// ---------------- helpers ----------------
__device__ __forceinline__ uint32_t pack_h2(float a, float b) {
    __half2 p = __floats2half2_rn(a, b);
    return *reinterpret_cast<uint32_t*>(&p);
}

// ---------------- conversion kernel ----------------
__global__ void conv_ew(const float* __restrict__ s, f16* __restrict__ d,
                        long long n4) {
    long long i = (long long)blockIdx.x * blockDim.x + threadIdx.x;
    if (i < n4) {
        float4 v = reinterpret_cast<const float4*>(s)[i];
        uint2 h;
        h.x = pack_h2(v.x, v.y); h.y = pack_h2(v.z, v.w);
        reinterpret_cast<uint2*>(d)[i] = h;
    }
}

// ---------------- GEMM tile config ----------------
constexpr int BM = 128, BN = 128, BK = 64;
constexpr int THREADS = 256;
constexpr int OFF_B  = 16384;                // A tile 16 KB
constexpr int STAGE  = 32768;                // + B tile 16 KB
constexpr int NSTG   = 3;
constexpr int SMEM_TOTAL = NSTG * STAGE;     // 96 KB -> 2 CTAs/SM

// A row-major tile: 128 rows x 128B (64 k x f16), swizzled
__device__ __forceinline__ int a_off(int m, int kc) {   // kc 0..7
    return m * 128 + ((kc ^ (m & 7)) << 4);
}
// B / ATR-A tile: 64 k-rows x 256B (128 elems), swizzled
__device__ __forceinline__ int b_off(int k, int nc) {   // nc 0..15
    return k * 256 + ((nc ^ (k & 7)) << 4);
}
__device__ __forceinline__ uint32_t smem_u32(const void* p) {
    uint32_t a;
    asm("{ .reg .u64 t; cvta.to.shared.u64 t, %1; cvt.u32.u64 %0, t; }"
        : "=r"(a) : "l"(p));
    return a;
}
__device__ __forceinline__ void ldsm4(uint32_t* r, uint32_t addr) {
    asm volatile("ldmatrix.sync.aligned.m8n8.x4.shared.b16 {%0,%1,%2,%3}, [%4];"
                 : "=r"(r[0]), "=r"(r[1]), "=r"(r[2]), "=r"(r[3]) : "r"(addr));
}
__device__ __forceinline__ void ldsm4t(uint32_t* r, uint32_t addr) {
    asm volatile("ldmatrix.sync.aligned.m8n8.x4.trans.shared.b16 {%0,%1,%2,%3}, [%4];"
                 : "=r"(r[0]), "=r"(r[1]), "=r"(r[2]), "=r"(r[3]) : "r"(addr));
}
__device__ __forceinline__ void mma_f16(float* d, const uint32_t* a, const uint32_t* b) {
    asm volatile(
        "mma.sync.aligned.m16n8k16.row.col.f32.f16.f16.f32 "
        "{%0,%1,%2,%3}, {%4,%5,%6,%7}, {%8,%9}, {%0,%1,%2,%3};"
        : "+f"(d[0]), "+f"(d[1]), "+f"(d[2]), "+f"(d[3])
        : "r"(a[0]), "r"(a[1]), "r"(a[2]), "r"(a[3]), "r"(b[0]), "r"(b[1]));
}
__device__ __forceinline__ void cp16(uint32_t dst, const void* src) {
    asm volatile("cp.async.cg.shared.global [%0], [%1], 16;" :: "r"(dst), "l"(src));
}
__device__ __forceinline__ void cp_commit() {
    asm volatile("cp.async.commit_group;" ::: "memory");
}
template<int N>
__device__ __forceinline__ void cp_wait() {
    asm volatile("cp.async.wait_group %0;" :: "n"(N) : "memory");
}

// ---------------- main GEMM kernel ----------------
// CTA 128x128, BK=64, warp tile 64x32, 2 CTAs/SM, fp16 in / fp32 accum.
// A-fragment double-buffered across the 4 kh sub-steps.
// ATR=1: A stored K-major [k][m] (dispatch mask); smem uses B-style layout + ldsm.trans.
// Two-level z indexing: off = (z/zMod)*s1 + (z%zMod)*s2; bias indexed by zr.
// OUTM: 0 = fp32 out, 2 = single f16 out.
template<int ATR, int OUTM, bool GELU_, bool BIAS_>
__global__ __launch_bounds__(THREADS, 2)
void moe_gemm(const f16* __restrict__ Ab, const f16* __restrict__ Bb,
              float* __restrict__ Cf, f16* __restrict__ Ch,
              const float* __restrict__ biasBase,
              int lda, int ldb, int ldc, int KT, int zMod,
              long long sA1, long long sA2, long long sB1, long long sB2,
              long long sC1, long long sC2, long long sBias2)
{
    extern __shared__ char smem[];
    const int tid  = threadIdx.x;
    const int lane = tid & 31;
    const int wid  = tid >> 5;
    const int wm   = (wid & 1) * 64;
    const int wn   = (wid >> 1) * 32;

    const int z = blockIdx.z;
    const int zq = z / zMod, zr = z % zMod;
    const f16* A = Ab + zq * sA1 + zr * sA2;
    const f16* B = Bb + zq * sB1 + zr * sB2;
    const long long coff = zq * sC1 + zr * sC2;
    const float* bias = BIAS_ ? biasBase + zr * sBias2 : nullptr;

    const int m0 = blockIdx.y * BM;
    const int n0 = blockIdx.x * BN;
    const uint32_t sbase = smem_u32(smem);

    float acc[4][4][4];
#pragma unroll
    for (int i = 0; i < 4; i++)
#pragma unroll
        for (int j = 0; j < 4; j++)
#pragma unroll
            for (int c = 0; c < 4; c++) acc[i][j][c] = 0.f;

    auto issue = [&](int it) {
        if (it < KT) {
            const uint32_t st = sbase + (it % NSTG) * STAGE;
            const int k0 = it * BK;
#pragma unroll
            for (int i = 0; i < 4; i++) {
                int c = tid + i * THREADS;          // 1024 chunks A
                if (ATR) {
                    int k = c >> 4, mc = c & 15;    // gmem row k, 16B m-chunk
                    cp16(st + b_off(k, mc),
                         A + (size_t)(k0 + k) * lda + m0 + mc * 8);
                } else {
                    int m = c >> 3, kc = c & 7;
                    cp16(st + a_off(m, kc),
                         A + (size_t)(m0 + m) * lda + k0 + kc * 8);
                }
            }
#pragma unroll
            for (int i = 0; i < 4; i++) {
                int c = tid + i * THREADS;          // 1024 chunks B
                int k = c >> 4, nc = c & 15;
                cp16(st + OFF_B + b_off(k, nc),
                     B + (size_t)(k0 + k) * ldb + n0 + nc * 8);
            }
        }
        cp_commit();
    };

    issue(0); issue(1);

    for (int it = 0; it < KT; ++it) {
        cp_wait<1>();
        __syncthreads();
        issue(it + 2);

        const uint32_t cur = sbase + (it % NSTG) * STAGE;

        auto loadA = [&](int kh, uint32_t (*ar)[4]) {
#pragma unroll
            for (int mf = 0; mf < 4; mf++) {
                if (ATR) {
                    int k = kh * 16 + (lane >> 4) * 8 + (lane & 7);
                    int mchunk = ((wm + mf * 16) >> 3) + ((lane >> 3) & 1);
                    ldsm4t(ar[mf], cur + b_off(k, mchunk));
                } else {
                    int row = wm + mf * 16 + (lane & 15);
                    int chunk = kh * 2 + (lane >> 4);
                    ldsm4(ar[mf], cur + a_off(row, chunk));
                }
            }
        };

        uint32_t arbuf[2][4][4];
        loadA(0, arbuf[0]);
#pragma unroll
        for (int kh = 0; kh < 4; kh++) {
            uint32_t br[2][4];
#pragma unroll
            for (int nb = 0; nb < 2; nb++) {
                int k = kh * 16 + ((lane >> 3) & 1) * 8 + (lane & 7);
                int nchunk = ((wn + nb * 16) >> 3) + (lane >> 4);
                ldsm4t(br[nb], cur + OFF_B + b_off(k, nchunk));
            }
            if (kh < 3) loadA(kh + 1, arbuf[(kh + 1) & 1]);
            uint32_t (*ar)[4] = arbuf[kh & 1];
#pragma unroll
            for (int mf = 0; mf < 4; mf++)
#pragma unroll
                for (int nf = 0; nf < 4; nf++)
                    mma_f16(acc[mf][nf], ar[mf], &br[nf >> 1][(nf & 1) * 2]);
        }
    }

    // ---- epilogue ----
    const int g = lane >> 2, t = lane & 3;
#pragma unroll
    for (int mf = 0; mf < 4; mf++) {
#pragma unroll
        for (int nf = 0; nf < 4; nf++) {
            int row = m0 + wm + mf * 16 + g;
            int col = n0 + wn + nf * 8 + t * 2;
            float v0 = acc[mf][nf][0], v1 = acc[mf][nf][1];
            float v2 = acc[mf][nf][2], v3 = acc[mf][nf][3];
            if (BIAS_) {
                float2 bv = *reinterpret_cast<const float2*>(bias + col);
                v0 += bv.x; v1 += bv.y; v2 += bv.x; v3 += bv.y;
            }
            if (GELU_) {
                v0 = 0.5f * v0 * (1.0f + erff(v0 * 0.70710678118654752f));
                v1 = 0.5f * v1 * (1.0f + erff(v1 * 0.70710678118654752f));
                v2 = 0.5f * v2 * (1.0f + erff(v2 * 0.70710678118654752f));
                v3 = 0.5f * v3 * (1.0f + erff(v3 * 0.70710678118654752f));
            }
            size_t o0 = (size_t)(coff + (size_t)row * ldc + col);
            size_t o1 = (size_t)(coff + (size_t)(row + 8) * ldc + col);
            if (OUTM == 0) {
                *reinterpret_cast<float2*>(Cf + o0) = make_float2(v0, v1);
                *reinterpret_cast<float2*>(Cf + o1) = make_float2(v2, v3);
            } else {
                *reinterpret_cast<uint32_t*>(Ch + o0) = pack_h2(v0, v1);
                *reinterpret_cast<uint32_t*>(Ch + o1) = pack_h2(v2, v3);
            }
        }
    }
}

// ---------------- launcher ----------------
extern "C" void kernel_launch(void* const* d_in, const int* in_sizes, int n_in,
                              void* d_out, int out_size)
{
    const float* x     = (const float*)d_in[0];
    const float* dmask = (const float*)d_in[1];
    const float* comb  = (const float*)d_in[2];
    const float* w1    = (const float*)d_in[3];
    const float* b1    = (const float*)d_in[4];
    const float* w2f   = (const float*)d_in[5];
    const float* b2    = (const float*)d_in[6];
    float* out = (float*)d_out;

    f16 *dm, *cmb, *xs, *w1s, *w2s, *xd, *hh, *yy;
    cudaGetSymbolAddress((void**)&dm,  g_dm);
    cudaGetSymbolAddress((void**)&cmb, g_cmb);
    cudaGetSymbolAddress((void**)&xs,  g_x);
    cudaGetSymbolAddress((void**)&w1s, g_w1);
    cudaGetSymbolAddress((void**)&w2s, g_w2);
    cudaGetSymbolAddress((void**)&xd,  g_xd);
    cudaGetSymbolAddress((void**)&hh,  g_h);
    cudaGetSymbolAddress((void**)&yy,  g_y);

    cudaFuncSetAttribute(moe_gemm<1, 2, false, false>,
                         cudaFuncAttributeMaxDynamicSharedMemorySize, SMEM_TOTAL);
    cudaFuncSetAttribute(moe_gemm<0, 2, true,  true>,
                         cudaFuncAttributeMaxDynamicSharedMemorySize, SMEM_TOTAL);
    cudaFuncSetAttribute(moe_gemm<0, 2, false, false>,
                         cudaFuncAttributeMaxDynamicSharedMemorySize, SMEM_TOTAL);
    cudaFuncSetAttribute(moe_gemm<0, 0, false, true>,
                         cudaFuncAttributeMaxDynamicSharedMemorySize, SMEM_TOTAL);

    // ---- conversions (elementwise fp16) ----
    {
        long long n4 = (long long)BDIM * TDIM * ECDIM / 4;
        conv_ew<<<(unsigned)((n4 + 255) / 256), 256>>>(dmask, dm, n4);
        conv_ew<<<(unsigned)((n4 + 255) / 256), 256>>>(comb, cmb, n4);
    }
    {
        long long n4 = (long long)BDIM * TDIM * DDIM / 4;
        conv_ew<<<(unsigned)((n4 + 255) / 256), 256>>>(x, xs, n4);
    }
    {
        long long n4 = (long long)EDIM * DDIM * HEDIM / 4;
        conv_ew<<<(unsigned)((n4 + 255) / 256), 256>>>(w1, w1s, n4);
        conv_ew<<<(unsigned)((n4 + 255) / 256), 256>>>(w2f, w2s, n4);
    }

    // ---- K1: xd[b][EC][D] = dmask_b^T[EC][T] @ x[b][T][D]  (ATR) ----
    moe_gemm<1, 2, false, false>
        <<<dim3(DDIM / BN, ECDIM / BM, BDIM), THREADS, SMEM_TOTAL>>>(
        dm, xs, nullptr, xd, nullptr,
        ECDIM, DDIM, DDIM, TDIM / BK, /*zMod*/ 1,
        (long long)TDIM * ECDIM, 0, (long long)TDIM * DDIM, 0,
        (long long)ECDIM * DDIM, 0, 0);

    // ---- K2: h[b,e][C][HE] = gelu(xd_{b,e}[C][D] @ w1_e[D][HE] + b1_e) ----
    moe_gemm<0, 2, true, true>
        <<<dim3(HEDIM / BN, CDIM / BM, BDIM * EDIM), THREADS, SMEM_TOTAL>>>(
        xd, w1s, nullptr, hh, b1,
        DDIM, HEDIM, HEDIM, DDIM / BK, /*zMod*/ EDIM,
        (long long)EDIM * CDIM * DDIM, (long long)CDIM * DDIM,
        0, (long long)DDIM * HEDIM,
        (long long)EDIM * CDIM * HEDIM, (long long)CDIM * HEDIM,
        (long long)HEDIM);

    // ---- K3: y[b,e][C][O] = h_{b,e}[C][HE] @ w2_e[HE][O] ----
    moe_gemm<0, 2, false, false>
        <<<dim3(ODIM / BN, CDIM / BM, BDIM * EDIM), THREADS, SMEM_TOTAL>>>(
        hh, w2s, nullptr, yy, nullptr,
        HEDIM, ODIM, ODIM, HEDIM / BK, /*zMod*/ EDIM,
        (long long)EDIM * CDIM * HEDIM, (long long)CDIM * HEDIM,
        0, (long long)HEDIM * ODIM,
        (long long)EDIM * CDIM * ODIM, (long long)CDIM * ODIM,
        0);

    // ---- K4: out[b][T][O] = comb[b][T][EC] @ y[b][EC][O] + b2 ----
    moe_gemm<0, 0, false, true>
        <<<dim3(ODIM / BN, TDIM / BM, BDIM), THREADS, SMEM_TOTAL>>>(
        cmb, yy, out, nullptr, b2,
        ECDIM, ODIM, ODIM, ECDIM / BK, /*zMod*/ 1,
        (long long)TDIM * ECDIM, 0, (long long)ECDIM * ODIM, 0,
        (long long)TDIM * ODIM, 0, 0);
}